// round 3
// baseline (speedup 1.0000x reference)
#include <cuda_runtime.h>
#include <math_constants.h>
#include <cstdint>

#define BB 32
#define SS 480
#define DD 512
#define HH 8
#define DK 64
#define ML 500
#define QT 32
#define JT 128
#define QTP 36
#define JTP 132

__device__ float g_q[BB*HH*SS*DK];
__device__ float g_k[BB*HH*SS*DK];
__device__ float g_v[BB*HH*SS*DK];
__device__ float g_ctx[(size_t)BB*SS*DD];

// ---------------------------------------------------------------------------
// tf32 helpers
// ---------------------------------------------------------------------------
__device__ __forceinline__ void split_tf32(float a, float& hi, float& lo) {
    uint32_t hb; asm("cvt.rna.tf32.f32 %0, %1;" : "=r"(hb) : "f"(a));
    hi = __uint_as_float(hb);
    float r = a - hi;
    uint32_t lb; asm("cvt.rna.tf32.f32 %0, %1;" : "=r"(lb) : "f"(r));
    lo = __uint_as_float(lb);
}

#define MMA_TF32(d, a0,a1,a2,a3, b0,b1) \
    asm volatile("mma.sync.aligned.m16n8k8.row.col.f32.tf32.tf32.f32 " \
        "{%0,%1,%2,%3}, {%4,%5,%6,%7}, {%8,%9}, {%0,%1,%2,%3};" \
        : "+f"(d[0]), "+f"(d[1]), "+f"(d[2]), "+f"(d[3]) \
        : "r"(a0), "r"(a1), "r"(a2), "r"(a3), "r"(b0), "r"(b1))

// ---------------------------------------------------------------------------
// Kernel 1: fused QKV projection via 3xTF32 mma.sync.
// CTA: 256 thr (8 warps, 4x2), tile 128 rows x 64 cols, BK=16.
// ---------------------------------------------------------------------------
__global__ __launch_bounds__(256) void proj_qkv(
    const float* __restrict__ x,
    const float* __restrict__ wq, const float* __restrict__ bq,
    const float* __restrict__ wk, const float* __restrict__ bk,
    const float* __restrict__ wv, const float* __restrict__ bv)
{
    const int z = blockIdx.z;
    const float* W    = (z == 0) ? wq : (z == 1) ? wk : wv;
    const float* bias = (z == 0) ? bq : (z == 1) ? bk : bv;
    float* Out        = (z == 0) ? g_q : (z == 1) ? g_k : g_v;

    __shared__ float Xh[16][132], Xl[16][132];   // [k][row]
    __shared__ float Wh[16][68],  Wl[16][68];    // [k][col]

    const int m0 = blockIdx.x * 64;
    const int n0 = blockIdx.y * 128;
    const int tid  = threadIdx.x;
    const int lane = tid & 31, warp = tid >> 5;
    const int g = lane >> 2, tig = lane & 3;
    const int wm = warp >> 1, wn = warp & 1;

    float acc[2][4][4] = {};

    for (int k0 = 0; k0 < DD; k0 += 16) {
        // load X tile (128 x 16) -> split hi/lo
#pragma unroll
        for (int i = 0; i < 2; i++) {
            int q = tid*2 + i;
            int r = q >> 2, c4 = q & 3;
            float4 v = *(const float4*)&x[(size_t)(n0 + r)*DD + k0 + c4*4];
            float vv[4] = {v.x, v.y, v.z, v.w};
#pragma unroll
            for (int j = 0; j < 4; j++) {
                float h_, l_; split_tf32(vv[j], h_, l_);
                Xh[c4*4+j][r] = h_; Xl[c4*4+j][r] = l_;
            }
        }
        // load W tile (16 x 64) -> split hi/lo
        {
            int kk = tid >> 4, c4 = tid & 15;
            float4 v = *(const float4*)&W[(size_t)(k0 + kk)*DD + m0 + c4*4];
            float vv[4] = {v.x, v.y, v.z, v.w};
#pragma unroll
            for (int j = 0; j < 4; j++) {
                float h_, l_; split_tf32(vv[j], h_, l_);
                Wh[kk][c4*4+j] = h_; Wl[kk][c4*4+j] = l_;
            }
        }
        __syncthreads();

#pragma unroll
        for (int ks = 0; ks < 2; ks++) {
            const int kA0 = ks*8 + tig, kA1 = ks*8 + tig + 4;
            uint32_t ah[2][4], al[2][4], bh[4][2], bl[4][2];
#pragma unroll
            for (int mt = 0; mt < 2; mt++) {
                int r0 = wm*32 + mt*16 + g;
                ah[mt][0] = __float_as_uint(Xh[kA0][r0]);
                ah[mt][1] = __float_as_uint(Xh[kA0][r0+8]);
                ah[mt][2] = __float_as_uint(Xh[kA1][r0]);
                ah[mt][3] = __float_as_uint(Xh[kA1][r0+8]);
                al[mt][0] = __float_as_uint(Xl[kA0][r0]);
                al[mt][1] = __float_as_uint(Xl[kA0][r0+8]);
                al[mt][2] = __float_as_uint(Xl[kA1][r0]);
                al[mt][3] = __float_as_uint(Xl[kA1][r0+8]);
            }
#pragma unroll
            for (int nt = 0; nt < 4; nt++) {
                int c = wn*32 + nt*8 + g;
                bh[nt][0] = __float_as_uint(Wh[kA0][c]);
                bh[nt][1] = __float_as_uint(Wh[kA1][c]);
                bl[nt][0] = __float_as_uint(Wl[kA0][c]);
                bl[nt][1] = __float_as_uint(Wl[kA1][c]);
            }
#pragma unroll
            for (int mt = 0; mt < 2; mt++)
#pragma unroll
                for (int nt = 0; nt < 4; nt++) {
                    MMA_TF32(acc[mt][nt], ah[mt][0],ah[mt][1],ah[mt][2],ah[mt][3], bh[nt][0],bh[nt][1]);
                    MMA_TF32(acc[mt][nt], ah[mt][0],ah[mt][1],ah[mt][2],ah[mt][3], bl[nt][0],bl[nt][1]);
                    MMA_TF32(acc[mt][nt], al[mt][0],al[mt][1],al[mt][2],al[mt][3], bh[nt][0],bh[nt][1]);
                }
        }
        __syncthreads();
    }

    // epilogue: scatter to [B,H,S,dk]
    const int h = m0 >> 6;
#pragma unroll
    for (int mt = 0; mt < 2; mt++) {
#pragma unroll
        for (int nt = 0; nt < 4; nt++) {
            int d = wn*32 + nt*8 + tig*2;       // col within 64-wide head block
            float b0 = bias[m0 + d], b1 = bias[m0 + d + 1];
#pragma unroll
            for (int half = 0; half < 2; half++) {
                int n = n0 + wm*32 + mt*16 + g + half*8;
                int b = n / SS, s = n % SS;
                float c0 = acc[mt][nt][half*2+0] + b0;
                float c1 = acc[mt][nt][half*2+1] + b1;
                *(float2*)&Out[(((size_t)b*HH + h)*SS + s)*DK + d] = make_float2(c0, c1);
            }
        }
    }
}

// ---------------------------------------------------------------------------
// Kernel 2: attention (unchanged from R2).
// ---------------------------------------------------------------------------
__global__ __launch_bounds__(512, 2) void attn_kernel(
    const float* __restrict__ rel_bias, float* __restrict__ out_attn)
{
    extern __shared__ float smem[];
    float* sc  = smem;
    float* qsT = sc + QT*SS;
    float* kvb = qsT + 64*QTP;

    const int b  = blockIdx.y;
    const int i0 = blockIdx.x * QT;
    const int tid = threadIdx.x;
    const int lane = tid & 31, warp = tid >> 5;

    const int jcount = i0 + QT;
    const int ntile  = (jcount + JT - 1) / JT;
    const int jcap   = min(SS, ntile * JT);

    const size_t abase = ((size_t)b*SS + i0)*SS;

    for (int h = 0; h < HH; h++) {
        const float* qg = g_q + (((size_t)b*HH + h)*SS + i0)*DK;
        const float* kg = g_k + (((size_t)b*HH + h)*SS)*DK;
        const float* vg = g_v + (((size_t)b*HH + h)*SS)*DK;
        __syncthreads();

        for (int idx = tid; idx < QT*DK; idx += 512) {
            int i = idx >> 6, t = idx & 63;
            qsT[t*QTP + i] = qg[idx];
        }

        for (int jt = 0; jt < ntile; jt++) {
            int j0 = jt * JT;
            __syncthreads();
            for (int idx = tid; idx < JT*DK; idx += 512) {
                int jl = idx >> 6, t = idx & 63;
                int j = j0 + jl;
                kvb[t*JTP + jl] = (j < SS) ? kg[(size_t)j*DK + t] : 0.f;
            }
            __syncthreads();
            const int ig = tid >> 6;
            const int jg = tid & 63;
            float acc[4][2] = {};
#pragma unroll
            for (int t = 0; t < 64; t++) {
                float4 a4 = *(const float4*)&qsT[t*QTP + ig*4];
                float2 b2 = *(const float2*)&kvb[t*JTP + jg*2];
                float av[4] = {a4.x, a4.y, a4.z, a4.w};
#pragma unroll
                for (int i = 0; i < 4; i++) {
                    acc[i][0] += av[i] * b2.x;
                    acc[i][1] += av[i] * b2.y;
                }
            }
#pragma unroll
            for (int ii = 0; ii < 4; ii++) {
                int i = i0 + ig*4 + ii;
                const float* brow = rel_bias + ((size_t)h*ML + i)*ML;
                int j0c = j0 + jg*2;
                float v0 = (j0c   <= i && j0c   < SS) ? acc[ii][0]*0.125f + brow[j0c]   : -CUDART_INF_F;
                float v1 = (j0c+1 <= i && j0c+1 < SS) ? acc[ii][1]*0.125f + brow[j0c+1] : -CUDART_INF_F;
                if (j0 + JT <= SS) {
                    *(float2*)&sc[(ig*4+ii)*SS + j0c] = make_float2(v0, v1);
                } else {
                    if (j0c   < SS) sc[(ig*4+ii)*SS + j0c]   = v0;
                    if (j0c+1 < SS) sc[(ig*4+ii)*SS + j0c+1] = v1;
                }
            }
        }
        __syncthreads();

        for (int r = warp; r < QT; r += 16) {
            float* row = sc + r*SS;
            float m = -CUDART_INF_F;
            for (int j = lane; j < jcap; j += 32) m = fmaxf(m, row[j]);
#pragma unroll
            for (int o = 16; o; o >>= 1) m = fmaxf(m, __shfl_xor_sync(0xffffffffu, m, o));
            float ssum = 0.f;
            for (int j = lane; j < jcap; j += 32) {
                float e = __expf(row[j] - m);
                row[j] = e;
                ssum += e;
            }
#pragma unroll
            for (int o = 16; o; o >>= 1) ssum += __shfl_xor_sync(0xffffffffu, ssum, o);
            float inv = 1.f / ssum;
            for (int j = lane; j < jcap; j += 32) row[j] *= inv;
        }
        __syncthreads();

        if (h == 0) {
            for (int i = 0; i < QT; i++) {
                float* dst = out_attn + abase + (size_t)i*SS;
                const float* src = sc + i*SS;
                for (int j = tid; j < SS; j += 512)
                    dst[j] = (j < jcap) ? src[j]*0.125f : 0.f;
            }
        } else {
            for (int i = 0; i < QT; i++) {
                float* dst = out_attn + abase + (size_t)i*SS;
                const float* src = sc + i*SS;
                for (int j = tid; j < jcap; j += 512)
                    dst[j] += src[j]*0.125f;
            }
        }

        {
            const int i = tid >> 4;
            const int dbase = (tid & 15) * 4;
            float a0 = 0.f, a1 = 0.f, a2 = 0.f, a3 = 0.f;
            for (int jt = 0; jt < ntile; jt++) {
                int j0 = jt * JT;
                __syncthreads();
                for (int idx = tid; idx < JT*DK; idx += 512) {
                    int j = j0 + (idx >> 6);
                    kvb[idx] = (j < SS) ? vg[(size_t)j*DK + (idx & 63)] : 0.f;
                }
                __syncthreads();
                int jlim = min(JT, jcap - j0);
                for (int jj = 0; jj < jlim; jj += 4) {
                    float4 p = *(const float4*)&sc[i*SS + j0 + jj];
                    float4 v0 = *(const float4*)&kvb[((jj+0) << 6) + dbase];
                    float4 v1 = *(const float4*)&kvb[((jj+1) << 6) + dbase];
                    float4 v2 = *(const float4*)&kvb[((jj+2) << 6) + dbase];
                    float4 v3 = *(const float4*)&kvb[((jj+3) << 6) + dbase];
                    a0 += p.x*v0.x + p.y*v1.x + p.z*v2.x + p.w*v3.x;
                    a1 += p.x*v0.y + p.y*v1.y + p.z*v2.y + p.w*v3.y;
                    a2 += p.x*v0.z + p.y*v1.z + p.z*v2.z + p.w*v3.z;
                    a3 += p.x*v0.w + p.y*v1.w + p.z*v2.w + p.w*v3.w;
                }
            }
            *(float4*)&g_ctx[((size_t)b*SS + i0 + i)*DD + h*DK + dbase] =
                make_float4(a0, a1, a2, a3);
        }
    }
}

// ---------------------------------------------------------------------------
// Kernel 3: output projection via 3xTF32 mma.sync (same scheme as proj_qkv).
// ---------------------------------------------------------------------------
__global__ __launch_bounds__(256) void out_proj(
    const float* __restrict__ wo, const float* __restrict__ bo,
    float* __restrict__ out)
{
    __shared__ float Xh[16][132], Xl[16][132];
    __shared__ float Wh[16][68],  Wl[16][68];

    const int m0 = blockIdx.x * 64;
    const int n0 = blockIdx.y * 128;
    const int tid  = threadIdx.x;
    const int lane = tid & 31, warp = tid >> 5;
    const int g = lane >> 2, tig = lane & 3;
    const int wm = warp >> 1, wn = warp & 1;

    float acc[2][4][4] = {};

    for (int k0 = 0; k0 < DD; k0 += 16) {
#pragma unroll
        for (int i = 0; i < 2; i++) {
            int q = tid*2 + i;
            int r = q >> 2, c4 = q & 3;
            float4 v = *(const float4*)&g_ctx[(size_t)(n0 + r)*DD + k0 + c4*4];
            float vv[4] = {v.x, v.y, v.z, v.w};
#pragma unroll
            for (int j = 0; j < 4; j++) {
                float h_, l_; split_tf32(vv[j], h_, l_);
                Xh[c4*4+j][r] = h_; Xl[c4*4+j][r] = l_;
            }
        }
        {
            int kk = tid >> 4, c4 = tid & 15;
            float4 v = *(const float4*)&wo[(size_t)(k0 + kk)*DD + m0 + c4*4];
            float vv[4] = {v.x, v.y, v.z, v.w};
#pragma unroll
            for (int j = 0; j < 4; j++) {
                float h_, l_; split_tf32(vv[j], h_, l_);
                Wh[kk][c4*4+j] = h_; Wl[kk][c4*4+j] = l_;
            }
        }
        __syncthreads();

#pragma unroll
        for (int ks = 0; ks < 2; ks++) {
            const int kA0 = ks*8 + tig, kA1 = ks*8 + tig + 4;
            uint32_t ah[2][4], al[2][4], bh[4][2], bl[4][2];
#pragma unroll
            for (int mt = 0; mt < 2; mt++) {
                int r0 = wm*32 + mt*16 + g;
                ah[mt][0] = __float_as_uint(Xh[kA0][r0]);
                ah[mt][1] = __float_as_uint(Xh[kA0][r0+8]);
                ah[mt][2] = __float_as_uint(Xh[kA1][r0]);
                ah[mt][3] = __float_as_uint(Xh[kA1][r0+8]);
                al[mt][0] = __float_as_uint(Xl[kA0][r0]);
                al[mt][1] = __float_as_uint(Xl[kA0][r0+8]);
                al[mt][2] = __float_as_uint(Xl[kA1][r0]);
                al[mt][3] = __float_as_uint(Xl[kA1][r0+8]);
            }
#pragma unroll
            for (int nt = 0; nt < 4; nt++) {
                int c = wn*32 + nt*8 + g;
                bh[nt][0] = __float_as_uint(Wh[kA0][c]);
                bh[nt][1] = __float_as_uint(Wh[kA1][c]);
                bl[nt][0] = __float_as_uint(Wl[kA0][c]);
                bl[nt][1] = __float_as_uint(Wl[kA1][c]);
            }
#pragma unroll
            for (int mt = 0; mt < 2; mt++)
#pragma unroll
                for (int nt = 0; nt < 4; nt++) {
                    MMA_TF32(acc[mt][nt], ah[mt][0],ah[mt][1],ah[mt][2],ah[mt][3], bh[nt][0],bh[nt][1]);
                    MMA_TF32(acc[mt][nt], ah[mt][0],ah[mt][1],ah[mt][2],ah[mt][3], bl[nt][0],bl[nt][1]);
                    MMA_TF32(acc[mt][nt], al[mt][0],al[mt][1],al[mt][2],al[mt][3], bh[nt][0],bh[nt][1]);
                }
        }
        __syncthreads();
    }

#pragma unroll
    for (int mt = 0; mt < 2; mt++) {
#pragma unroll
        for (int nt = 0; nt < 4; nt++) {
            int m = m0 + wn*32 + nt*8 + tig*2;
            float b0 = bo[m], b1 = bo[m + 1];
#pragma unroll
            for (int half = 0; half < 2; half++) {
                int n = n0 + wm*32 + mt*16 + g + half*8;
                float c0 = acc[mt][nt][half*2+0] + b0;
                float c1 = acc[mt][nt][half*2+1] + b1;
                *(float2*)&out[(size_t)n*DD + m] = make_float2(c0, c1);
            }
        }
    }
}

// ---------------------------------------------------------------------------

static const int ATTN_SMEM = (QT*SS + 64*QTP + 64*JTP) * (int)sizeof(float); // 104448

extern "C" void kernel_launch(void* const* d_in, const int* in_sizes, int n_in,
                              void* d_out, int out_size) {
    const float* x  = (const float*)d_in[0];
    const float* wq = (const float*)d_in[1];
    const float* bq = (const float*)d_in[2];
    const float* wk = (const float*)d_in[3];
    const float* bk = (const float*)d_in[4];
    const float* wv = (const float*)d_in[5];
    const float* bv = (const float*)d_in[6];
    const float* wo = (const float*)d_in[7];
    const float* bo = (const float*)d_in[8];
    const float* rb = (const float*)d_in[9];

    float* out      = (float*)d_out;
    float* out_attn = out + (size_t)BB*SS*DD;

    proj_qkv<<<dim3(DD/64, (BB*SS)/128, 3), 256>>>(x, wq, bq, wk, bk, wv, bv);

    cudaFuncSetAttribute(attn_kernel, cudaFuncAttributeMaxDynamicSharedMemorySize, ATTN_SMEM);
    attn_kernel<<<dim3(SS/QT, BB), 512, ATTN_SMEM>>>(rb, out_attn);

    out_proj<<<dim3(DD/64, (BB*SS)/128), 256>>>(wo, bo, out);
}

// round 4
// speedup vs baseline: 1.0502x; 1.0502x over previous
#include <cuda_runtime.h>
#include <math_constants.h>
#include <cstdint>

#define BB 32
#define SS 480
#define DD 512
#define HH 8
#define DK 64
#define ML 500
#define QT 32
#define JT 128
#define QTP 36
#define JTP 132

__device__ float g_q[BB*HH*SS*DK];
__device__ float g_k[BB*HH*SS*DK];
__device__ float g_v[BB*HH*SS*DK];
__device__ float g_ctx[(size_t)BB*SS*DD];
__device__ float g_p[(size_t)BB*HH*SS*SS];   // probs, 236 MB

// ---------------------------------------------------------------------------
// Kernel 1: fused QKV projection (FFMA, R2 version — 520us known).
// ---------------------------------------------------------------------------
__global__ __launch_bounds__(256) void proj_qkv(
    const float* __restrict__ x,
    const float* __restrict__ wq, const float* __restrict__ bq,
    const float* __restrict__ wk, const float* __restrict__ bk,
    const float* __restrict__ wv, const float* __restrict__ bv)
{
    const int z = blockIdx.z;
    const float* W    = (z == 0) ? wq : (z == 1) ? wk : wv;
    const float* bias = (z == 0) ? bq : (z == 1) ? bk : bv;
    float* Out        = (z == 0) ? g_q : (z == 1) ? g_k : g_v;

    __shared__ float Xs[32][132];
    __shared__ float Ws[32][68];

    const int m0 = blockIdx.x * 64;
    const int n0 = blockIdx.y * 128;
    const int tid = threadIdx.x;

    const int c8 = tid & 7, xr = tid >> 3;
    const int wc = tid & 63, wt = tid >> 6;
    const int ri = tid >> 4, ci = tid & 15;

    float acc[8][4] = {};

    for (int k0 = 0; k0 < DD; k0 += 32) {
#pragma unroll
        for (int rr = 0; rr < 4; rr++) {
            int r = xr + rr*32;
            float4 v = *(const float4*)&x[(size_t)(n0 + r)*DD + k0 + c8*4];
            Xs[c8*4+0][r] = v.x; Xs[c8*4+1][r] = v.y;
            Xs[c8*4+2][r] = v.z; Xs[c8*4+3][r] = v.w;
        }
#pragma unroll
        for (int tt = 0; tt < 8; tt++)
            Ws[wt + tt*4][wc] = W[(size_t)(k0 + wt + tt*4)*DD + m0 + wc];
        __syncthreads();
#pragma unroll
        for (int t = 0; t < 32; t++) {
            float4 a0 = *(const float4*)&Xs[t][ri*8];
            float4 a1 = *(const float4*)&Xs[t][ri*8+4];
            float4 b4 = *(const float4*)&Ws[t][ci*4];
            float av[8] = {a0.x,a0.y,a0.z,a0.w,a1.x,a1.y,a1.z,a1.w};
            float bw[4] = {b4.x,b4.y,b4.z,b4.w};
#pragma unroll
            for (int i = 0; i < 8; i++)
#pragma unroll
                for (int j = 0; j < 4; j++)
                    acc[i][j] += av[i] * bw[j];
        }
        __syncthreads();
    }

    const float4 bb = *(const float4*)&bias[m0 + ci*4];
    const int h = m0 >> 6;
    const int dbase = ci*4;
#pragma unroll
    for (int u = 0; u < 8; u++) {
        int n = n0 + ri*8 + u;
        int b = n / SS, s = n % SS;
        float4 o = make_float4(acc[u][0]+bb.x, acc[u][1]+bb.y,
                               acc[u][2]+bb.z, acc[u][3]+bb.w);
        *(float4*)&Out[(((size_t)b*HH + h)*SS + s)*DK + dbase] = o;
    }
}

// ---------------------------------------------------------------------------
// Kernel 2: scores + softmax + write probs P.  CTA per (b, h, 32-row tile).
// ---------------------------------------------------------------------------
__global__ __launch_bounds__(256, 2) void scores_kernel(
    const float* __restrict__ rel_bias)
{
    extern __shared__ float smem[];
    float* sc  = smem;             // QT*SS
    float* qsT = sc + QT*SS;       // 64*QTP
    float* kvb = qsT + 64*QTP;     // 64*JTP

    const int i0 = blockIdx.x * QT;
    const int h  = blockIdx.y;
    const int b  = blockIdx.z;
    const int tid = threadIdx.x;
    const int lane = tid & 31, warp = tid >> 5;

    const int jcount = i0 + QT;
    const int ntile  = (jcount + JT - 1) / JT;
    const int jcap   = min(SS, ntile * JT);

    const float* qg = g_q + (((size_t)b*HH + h)*SS + i0)*DK;
    const float* kg = g_k + (((size_t)b*HH + h)*SS)*DK;

    // q tile transposed
    for (int idx = tid; idx < QT*DK; idx += 256) {
        int i = idx >> 6, t = idx & 63;
        qsT[t*QTP + i] = qg[idx];
    }

    for (int jt = 0; jt < ntile; jt++) {
        int j0 = jt * JT;
        __syncthreads();
        for (int idx = tid; idx < JT*DK; idx += 256) {
            int jl = idx >> 6, t = idx & 63;
            int j = j0 + jl;
            kvb[t*JTP + jl] = (j < SS) ? kg[(size_t)j*DK + t] : 0.f;
        }
        __syncthreads();
        const int ti = (tid >> 5) * 4;       // 8 row groups of 4
        const int tj = (tid & 31) * 4;       // 32 col groups of 4
        float acc[4][4] = {};
#pragma unroll
        for (int t = 0; t < 64; t++) {
            float4 a4 = *(const float4*)&qsT[t*QTP + ti];
            float4 b4 = *(const float4*)&kvb[t*JTP + tj];
            float av[4] = {a4.x, a4.y, a4.z, a4.w};
            float bw[4] = {b4.x, b4.y, b4.z, b4.w};
#pragma unroll
            for (int i = 0; i < 4; i++)
#pragma unroll
                for (int j = 0; j < 4; j++)
                    acc[i][j] += av[i] * bw[j];
        }
#pragma unroll
        for (int ii = 0; ii < 4; ii++) {
            int i = i0 + ti + ii;
            const float* brow = rel_bias + ((size_t)h*ML + i)*ML;
            float4 bias4;
            if (j0 + tj + 3 < SS) bias4 = *(const float4*)&brow[j0 + tj];
            else {
                bias4.x = (j0+tj   < SS) ? brow[j0+tj]   : 0.f;
                bias4.y = (j0+tj+1 < SS) ? brow[j0+tj+1] : 0.f;
                bias4.z = (j0+tj+2 < SS) ? brow[j0+tj+2] : 0.f;
                bias4.w = (j0+tj+3 < SS) ? brow[j0+tj+3] : 0.f;
            }
            float bb4[4] = {bias4.x, bias4.y, bias4.z, bias4.w};
            float vals[4];
#pragma unroll
            for (int jj = 0; jj < 4; jj++) {
                int j = j0 + tj + jj;
                vals[jj] = (j <= i && j < SS) ? acc[ii][jj]*0.125f + bb4[jj]
                                              : -CUDART_INF_F;
            }
            if (j0 + JT <= SS) {
                *(float4*)&sc[(ti+ii)*SS + j0 + tj] =
                    make_float4(vals[0], vals[1], vals[2], vals[3]);
            } else {
#pragma unroll
                for (int jj = 0; jj < 4; jj++) {
                    int j = j0 + tj + jj;
                    if (j < SS) sc[(ti+ii)*SS + j] = vals[jj];
                }
            }
        }
    }
    __syncthreads();

    // softmax: 8 warps, 4 rows each
    for (int r = warp; r < QT; r += 8) {
        float* row = sc + r*SS;
        float m = -CUDART_INF_F;
        for (int j = lane; j < jcap; j += 32) m = fmaxf(m, row[j]);
#pragma unroll
        for (int o = 16; o; o >>= 1) m = fmaxf(m, __shfl_xor_sync(0xffffffffu, m, o));
        float ssum = 0.f;
        for (int j = lane; j < jcap; j += 32) {
            float e = __expf(row[j] - m);
            row[j] = e;
            ssum += e;
        }
#pragma unroll
        for (int o = 16; o; o >>= 1) ssum += __shfl_xor_sync(0xffffffffu, ssum, o);
        float inv = 1.f / ssum;
        for (int j = lane; j < jcap; j += 32) row[j] *= inv;
    }
    __syncthreads();

    // write probs (float4, coalesced). Masked entries are exact zeros.
    float* pg = g_p + (((size_t)b*HH + h)*SS + i0)*SS;
    const int nq4 = jcap >> 2;
    for (int idx = tid; idx < QT*nq4; idx += 256) {
        int r = idx / nq4, c4 = idx - r*nq4;
        *(float4*)&pg[(size_t)r*SS + c4*4] = *(const float4*)&sc[r*SS + c4*4];
    }
}

// ---------------------------------------------------------------------------
// Kernel 3: attn mean over heads.  One float4 per thread.
// ---------------------------------------------------------------------------
__global__ __launch_bounds__(256) void mean_kernel(float* __restrict__ out_attn)
{
    const int gid = blockIdx.x * 256 + threadIdx.x;         // < BB*SS*120
    const int j4  = gid % (SS/4);
    int rest = gid / (SS/4);
    const int i = rest % SS;
    const int b = rest / SS;

    const int i0 = (i >> 5) << 5;
    const int jcap = min(SS, (((i0 + QT) + JT - 1) / JT) * JT);

    float4 s = make_float4(0.f, 0.f, 0.f, 0.f);
    if (j4*4 < jcap) {
        const float* base = g_p + (((size_t)b*HH)*SS + i)*SS + j4*4;
#pragma unroll
        for (int h = 0; h < HH; h++) {
            float4 v = *(const float4*)(base + (size_t)h*SS*SS);
            s.x += v.x; s.y += v.y; s.z += v.z; s.w += v.w;
        }
        s.x *= 0.125f; s.y *= 0.125f; s.z *= 0.125f; s.w *= 0.125f;
    }
    *(float4*)&out_attn[((size_t)b*SS + i)*SS + j4*4] = s;
}

// ---------------------------------------------------------------------------
// Kernel 4: ctx = P @ V.  CTA per (b, h, 32-row tile).  V in smem,
// P via broadcast LDG (L2).
// ---------------------------------------------------------------------------
__global__ __launch_bounds__(256) void pv_kernel()
{
    __shared__ float vs[JT][68];

    const int i0 = blockIdx.x * QT;
    const int h  = blockIdx.y;
    const int b  = blockIdx.z;
    const int tid = threadIdx.x;

    const int jcount = i0 + QT;
    const int ntile  = (jcount + JT - 1) / JT;
    const int jcap   = min(SS, ntile * JT);

    const float* vg = g_v + (((size_t)b*HH + h)*SS)*DK;
    const float* pg = g_p + (((size_t)b*HH + h)*SS + i0)*SS;

    const int r = tid >> 3;               // 32 rows
    const int dbase = (tid & 7) * 8;      // 8 d-groups of 8

    float acc[8] = {};

    for (int jt = 0; jt < ntile; jt++) {
        int j0 = jt * JT;
        __syncthreads();
        for (int idx = tid; idx < JT*DK; idx += 256) {
            int j = j0 + (idx >> 6);
            vs[idx >> 6][idx & 63] = (j < SS) ? vg[(size_t)j*DK + (idx & 63)] : 0.f;
        }
        __syncthreads();
        int jlim = min(JT, jcap - j0);
        const float* prow = pg + (size_t)r*SS + j0;
        for (int jj = 0; jj < jlim; jj += 4) {
            float4 p = *(const float4*)&prow[jj];
            float4 v00 = *(const float4*)&vs[jj+0][dbase];
            float4 v01 = *(const float4*)&vs[jj+0][dbase+4];
            float4 v10 = *(const float4*)&vs[jj+1][dbase];
            float4 v11 = *(const float4*)&vs[jj+1][dbase+4];
            float4 v20 = *(const float4*)&vs[jj+2][dbase];
            float4 v21 = *(const float4*)&vs[jj+2][dbase+4];
            float4 v30 = *(const float4*)&vs[jj+3][dbase];
            float4 v31 = *(const float4*)&vs[jj+3][dbase+4];
            acc[0] += p.x*v00.x + p.y*v10.x + p.z*v20.x + p.w*v30.x;
            acc[1] += p.x*v00.y + p.y*v10.y + p.z*v20.y + p.w*v30.y;
            acc[2] += p.x*v00.z + p.y*v10.z + p.z*v20.z + p.w*v30.z;
            acc[3] += p.x*v00.w + p.y*v10.w + p.z*v20.w + p.w*v30.w;
            acc[4] += p.x*v01.x + p.y*v11.x + p.z*v21.x + p.w*v31.x;
            acc[5] += p.x*v01.y + p.y*v11.y + p.z*v21.y + p.w*v31.y;
            acc[6] += p.x*v01.z + p.y*v11.z + p.z*v21.z + p.w*v31.z;
            acc[7] += p.x*v01.w + p.y*v11.w + p.z*v21.w + p.w*v31.w;
        }
    }

    float* dst = g_ctx + ((size_t)b*SS + i0 + r)*DD + h*DK + dbase;
    *(float4*)&dst[0] = make_float4(acc[0], acc[1], acc[2], acc[3]);
    *(float4*)&dst[4] = make_float4(acc[4], acc[5], acc[6], acc[7]);
}

// ---------------------------------------------------------------------------
// Kernel 5: output projection (FFMA, R2 version).
// ---------------------------------------------------------------------------
__global__ __launch_bounds__(256) void out_proj(
    const float* __restrict__ wo, const float* __restrict__ bo,
    float* __restrict__ out)
{
    __shared__ float Xs[32][132];
    __shared__ float Ws[32][68];

    const int m0 = blockIdx.x * 64;
    const int n0 = blockIdx.y * 128;
    const int tid = threadIdx.x;

    const int c8 = tid & 7, xr = tid >> 3;
    const int wc = tid & 63, wt = tid >> 6;
    const int ri = tid >> 4, ci = tid & 15;

    float acc[8][4] = {};

    for (int k0 = 0; k0 < DD; k0 += 32) {
#pragma unroll
        for (int rr = 0; rr < 4; rr++) {
            int r = xr + rr*32;
            float4 v = *(const float4*)&g_ctx[(size_t)(n0 + r)*DD + k0 + c8*4];
            Xs[c8*4+0][r] = v.x; Xs[c8*4+1][r] = v.y;
            Xs[c8*4+2][r] = v.z; Xs[c8*4+3][r] = v.w;
        }
#pragma unroll
        for (int tt = 0; tt < 8; tt++)
            Ws[wt + tt*4][wc] = wo[(size_t)(k0 + wt + tt*4)*DD + m0 + wc];
        __syncthreads();
#pragma unroll
        for (int t = 0; t < 32; t++) {
            float4 a0 = *(const float4*)&Xs[t][ri*8];
            float4 a1 = *(const float4*)&Xs[t][ri*8+4];
            float4 b4 = *(const float4*)&Ws[t][ci*4];
            float av[8] = {a0.x,a0.y,a0.z,a0.w,a1.x,a1.y,a1.z,a1.w};
            float bw[4] = {b4.x,b4.y,b4.z,b4.w};
#pragma unroll
            for (int i = 0; i < 8; i++)
#pragma unroll
                for (int j = 0; j < 4; j++)
                    acc[i][j] += av[i] * bw[j];
        }
        __syncthreads();
    }

    const float4 bb = *(const float4*)&bo[m0 + ci*4];
#pragma unroll
    for (int u = 0; u < 8; u++) {
        int n = n0 + ri*8 + u;
        float4 o = make_float4(acc[u][0]+bb.x, acc[u][1]+bb.y,
                               acc[u][2]+bb.z, acc[u][3]+bb.w);
        *(float4*)&out[(size_t)n*DD + m0 + ci*4] = o;
    }
}

// ---------------------------------------------------------------------------

static const int SC_SMEM = (QT*SS + 64*QTP + 64*JTP) * (int)sizeof(float); // 104448

extern "C" void kernel_launch(void* const* d_in, const int* in_sizes, int n_in,
                              void* d_out, int out_size) {
    const float* x  = (const float*)d_in[0];
    const float* wq = (const float*)d_in[1];
    const float* bq = (const float*)d_in[2];
    const float* wk = (const float*)d_in[3];
    const float* bk = (const float*)d_in[4];
    const float* wv = (const float*)d_in[5];
    const float* bv = (const float*)d_in[6];
    const float* wo = (const float*)d_in[7];
    const float* bo = (const float*)d_in[8];
    const float* rb = (const float*)d_in[9];

    float* out      = (float*)d_out;
    float* out_attn = out + (size_t)BB*SS*DD;

    proj_qkv<<<dim3(DD/64, (BB*SS)/128, 3), 256>>>(x, wq, bq, wk, bk, wv, bv);

    cudaFuncSetAttribute(scores_kernel, cudaFuncAttributeMaxDynamicSharedMemorySize, SC_SMEM);
    scores_kernel<<<dim3(SS/QT, HH, BB), 256, SC_SMEM>>>(rb);

    mean_kernel<<<(BB*SS*(SS/4))/256, 256>>>(out_attn);

    pv_kernel<<<dim3(SS/QT, HH, BB), 256>>>();

    out_proj<<<dim3(DD/64, (BB*SS)/128), 256>>>(wo, bo, out);
}

// round 5
// speedup vs baseline: 1.3124x; 1.2496x over previous
#include <cuda_runtime.h>
#include <math_constants.h>
#include <cstdint>

#define BB 32
#define SS 480
#define DD 512
#define HH 8
#define DK 64
#define ML 500
#define QT 32
#define JT 128
#define QTP 36
#define JTP 132
#define PTS 36     // psT row stride (16B-aligned, 4-way store conflict tolerated)

__device__ float g_q[BB*HH*SS*DK];
__device__ float g_k[BB*HH*SS*DK];
__device__ float g_v[BB*HH*SS*DK];
__device__ float g_ctx[(size_t)BB*SS*DD];
__device__ float g_p[(size_t)BB*HH*SS*SS];   // probs, 236 MB

// ---------------------------------------------------------------------------
// Kernel 1: fused QKV projection.  128 threads, tile 128x64, thread tile 8x8.
// ---------------------------------------------------------------------------
__global__ __launch_bounds__(128) void proj_qkv(
    const float* __restrict__ x,
    const float* __restrict__ wq, const float* __restrict__ bq,
    const float* __restrict__ wk, const float* __restrict__ bk,
    const float* __restrict__ wv, const float* __restrict__ bv)
{
    const int z = blockIdx.z;
    const float* W    = (z == 0) ? wq : (z == 1) ? wk : wv;
    const float* bias = (z == 0) ? bq : (z == 1) ? bk : bv;
    float* Out        = (z == 0) ? g_q : (z == 1) ? g_k : g_v;

    __shared__ float Xs[32][132];
    __shared__ float Ws[32][68];

    const int m0 = blockIdx.x * 64;
    const int n0 = blockIdx.y * 128;
    const int tid = threadIdx.x;

    const int c8 = tid & 7,  xrow = tid >> 3;   // X: float4 col, row base (16 rows)
    const int wc4 = tid & 15, wk_ = tid >> 4;   // W: float4 col, k base (8)
    const int ri = tid >> 3, ci = tid & 7;      // compute: 16 rowgroups x 8 colgroups

    float acc[8][8] = {};

    for (int k0 = 0; k0 < DD; k0 += 32) {
#pragma unroll
        for (int rr = 0; rr < 8; rr++) {
            int r = xrow + rr*16;
            float4 v = *(const float4*)&x[(size_t)(n0 + r)*DD + k0 + c8*4];
            Xs[c8*4+0][r] = v.x; Xs[c8*4+1][r] = v.y;
            Xs[c8*4+2][r] = v.z; Xs[c8*4+3][r] = v.w;
        }
#pragma unroll
        for (int tt = 0; tt < 4; tt++) {
            int k = wk_ + tt*8;
            float4 v = *(const float4*)&W[(size_t)(k0 + k)*DD + m0 + wc4*4];
            *(float4*)&Ws[k][wc4*4] = v;
        }
        __syncthreads();
#pragma unroll
        for (int t = 0; t < 32; t++) {
            float4 a0 = *(const float4*)&Xs[t][ri*8];
            float4 a1 = *(const float4*)&Xs[t][ri*8+4];
            float4 b0 = *(const float4*)&Ws[t][ci*8];
            float4 b1 = *(const float4*)&Ws[t][ci*8+4];
            float av[8] = {a0.x,a0.y,a0.z,a0.w,a1.x,a1.y,a1.z,a1.w};
            float bw[8] = {b0.x,b0.y,b0.z,b0.w,b1.x,b1.y,b1.z,b1.w};
#pragma unroll
            for (int i = 0; i < 8; i++)
#pragma unroll
                for (int j = 0; j < 8; j++)
                    acc[i][j] += av[i] * bw[j];
        }
        __syncthreads();
    }

    const int h = m0 >> 6;
    const int d = ci*8;
    float4 bb0 = *(const float4*)&bias[m0 + d];
    float4 bb1 = *(const float4*)&bias[m0 + d + 4];
#pragma unroll
    for (int u = 0; u < 8; u++) {
        int n = n0 + ri*8 + u;
        int b = n / SS, s = n % SS;
        float* dst = &Out[(((size_t)b*HH + h)*SS + s)*DK + d];
        *(float4*)&dst[0] = make_float4(acc[u][0]+bb0.x, acc[u][1]+bb0.y,
                                        acc[u][2]+bb0.z, acc[u][3]+bb0.w);
        *(float4*)&dst[4] = make_float4(acc[u][4]+bb1.x, acc[u][5]+bb1.y,
                                        acc[u][6]+bb1.z, acc[u][7]+bb1.w);
    }
}

// ---------------------------------------------------------------------------
// Kernel 2: scores + softmax + write probs P.  (unchanged)
// ---------------------------------------------------------------------------
__global__ __launch_bounds__(256, 2) void scores_kernel(
    const float* __restrict__ rel_bias)
{
    extern __shared__ float smem[];
    float* sc  = smem;             // QT*SS
    float* qsT = sc + QT*SS;       // 64*QTP
    float* kvb = qsT + 64*QTP;     // 64*JTP

    const int i0 = blockIdx.x * QT;
    const int h  = blockIdx.y;
    const int b  = blockIdx.z;
    const int tid = threadIdx.x;
    const int lane = tid & 31, warp = tid >> 5;

    const int jcount = i0 + QT;
    const int ntile  = (jcount + JT - 1) / JT;
    const int jcap   = min(SS, ntile * JT);

    const float* qg = g_q + (((size_t)b*HH + h)*SS + i0)*DK;
    const float* kg = g_k + (((size_t)b*HH + h)*SS)*DK;

    for (int idx = tid; idx < QT*DK; idx += 256) {
        int i = idx >> 6, t = idx & 63;
        qsT[t*QTP + i] = qg[idx];
    }

    for (int jt = 0; jt < ntile; jt++) {
        int j0 = jt * JT;
        __syncthreads();
        for (int idx = tid; idx < JT*DK; idx += 256) {
            int jl = idx >> 6, t = idx & 63;
            int j = j0 + jl;
            kvb[t*JTP + jl] = (j < SS) ? kg[(size_t)j*DK + t] : 0.f;
        }
        __syncthreads();
        const int ti = (tid >> 5) * 4;
        const int tj = (tid & 31) * 4;
        float acc[4][4] = {};
#pragma unroll
        for (int t = 0; t < 64; t++) {
            float4 a4 = *(const float4*)&qsT[t*QTP + ti];
            float4 b4 = *(const float4*)&kvb[t*JTP + tj];
            float av[4] = {a4.x, a4.y, a4.z, a4.w};
            float bw[4] = {b4.x, b4.y, b4.z, b4.w};
#pragma unroll
            for (int i = 0; i < 4; i++)
#pragma unroll
                for (int j = 0; j < 4; j++)
                    acc[i][j] += av[i] * bw[j];
        }
#pragma unroll
        for (int ii = 0; ii < 4; ii++) {
            int i = i0 + ti + ii;
            const float* brow = rel_bias + ((size_t)h*ML + i)*ML;
            float4 bias4;
            if (j0 + tj + 3 < SS) bias4 = *(const float4*)&brow[j0 + tj];
            else {
                bias4.x = (j0+tj   < SS) ? brow[j0+tj]   : 0.f;
                bias4.y = (j0+tj+1 < SS) ? brow[j0+tj+1] : 0.f;
                bias4.z = (j0+tj+2 < SS) ? brow[j0+tj+2] : 0.f;
                bias4.w = (j0+tj+3 < SS) ? brow[j0+tj+3] : 0.f;
            }
            float bb4[4] = {bias4.x, bias4.y, bias4.z, bias4.w};
            float vals[4];
#pragma unroll
            for (int jj = 0; jj < 4; jj++) {
                int j = j0 + tj + jj;
                vals[jj] = (j <= i && j < SS) ? acc[ii][jj]*0.125f + bb4[jj]
                                              : -CUDART_INF_F;
            }
            if (j0 + JT <= SS) {
                *(float4*)&sc[(ti+ii)*SS + j0 + tj] =
                    make_float4(vals[0], vals[1], vals[2], vals[3]);
            } else {
#pragma unroll
                for (int jj = 0; jj < 4; jj++) {
                    int j = j0 + tj + jj;
                    if (j < SS) sc[(ti+ii)*SS + j] = vals[jj];
                }
            }
        }
    }
    __syncthreads();

    for (int r = warp; r < QT; r += 8) {
        float* row = sc + r*SS;
        float m = -CUDART_INF_F;
        for (int j = lane; j < jcap; j += 32) m = fmaxf(m, row[j]);
#pragma unroll
        for (int o = 16; o; o >>= 1) m = fmaxf(m, __shfl_xor_sync(0xffffffffu, m, o));
        float ssum = 0.f;
        for (int j = lane; j < jcap; j += 32) {
            float e = __expf(row[j] - m);
            row[j] = e;
            ssum += e;
        }
#pragma unroll
        for (int o = 16; o; o >>= 1) ssum += __shfl_xor_sync(0xffffffffu, ssum, o);
        float inv = 1.f / ssum;
        for (int j = lane; j < jcap; j += 32) row[j] *= inv;
    }
    __syncthreads();

    float* pg = g_p + (((size_t)b*HH + h)*SS + i0)*SS;
    const int nq4 = jcap >> 2;
    for (int idx = tid; idx < QT*nq4; idx += 256) {
        int r = idx / nq4, c4 = idx - r*nq4;
        *(float4*)&pg[(size_t)r*SS + c4*4] = *(const float4*)&sc[r*SS + c4*4];
    }
}

// ---------------------------------------------------------------------------
// Kernel 3: attn mean over heads.  (unchanged)
// ---------------------------------------------------------------------------
__global__ __launch_bounds__(256) void mean_kernel(float* __restrict__ out_attn)
{
    const int gid = blockIdx.x * 256 + threadIdx.x;
    const int j4  = gid % (SS/4);
    int rest = gid / (SS/4);
    const int i = rest % SS;
    const int b = rest / SS;

    const int i0 = (i >> 5) << 5;
    const int jcap = min(SS, (((i0 + QT) + JT - 1) / JT) * JT);

    float4 s = make_float4(0.f, 0.f, 0.f, 0.f);
    if (j4*4 < jcap) {
        const float* base = g_p + (((size_t)b*HH)*SS + i)*SS + j4*4;
#pragma unroll
        for (int h = 0; h < HH; h++) {
            float4 v = *(const float4*)(base + (size_t)h*SS*SS);
            s.x += v.x; s.y += v.y; s.z += v.z; s.w += v.w;
        }
        s.x *= 0.125f; s.y *= 0.125f; s.z *= 0.125f; s.w *= 0.125f;
    }
    *(float4*)&out_attn[((size_t)b*SS + i)*SS + j4*4] = s;
}

// ---------------------------------------------------------------------------
// Kernel 4: ctx = P @ V.  Register-tiled GEMM: 128 threads, C tile 32x64,
// thread tile 4x4.  P transposed in smem (psT[j][r]), V as vs[j][d].
// Per j-step: 2x LDS.128 -> 16 FMA, 16 independent accumulators.
// ---------------------------------------------------------------------------
__global__ __launch_bounds__(128) void pv_kernel()
{
    extern __shared__ float pvsm[];
    float* psT = pvsm;              // JT * PTS
    float* vs  = psT + JT*PTS;      // JT * 64

    const int i0 = blockIdx.x * QT;
    const int h  = blockIdx.y;
    const int b  = blockIdx.z;
    const int tid = threadIdx.x;

    const int jcount = i0 + QT;
    const int ntile  = (jcount + JT - 1) / JT;

    const float* vg = g_v + (((size_t)b*HH + h)*SS)*DK;
    const float* pg = g_p + (((size_t)b*HH + h)*SS + i0)*SS;

    const int rg = tid >> 4;      // 8 rowgroups of 4  (32 rows)
    const int cg = tid & 15;      // 16 colgroups of 4 (64 cols)

    float acc[4][4] = {};

    for (int jt = 0; jt < ntile; jt++) {
        const int j0 = jt * JT;
        __syncthreads();
        // V tile: [j][d], coalesced float4 loads
#pragma unroll
        for (int it = 0; it < 16; it++) {
            int idx = tid + it*128;               // 2048 float4 total
            int j = idx >> 4, d4 = idx & 15;
            float4 v = (j0 + j < SS)
                ? *(const float4*)&vg[(size_t)(j0 + j)*DK + d4*4]
                : make_float4(0.f,0.f,0.f,0.f);
            *(float4*)&vs[j*64 + d4*4] = v;
        }
        // P tile transposed: read coalesced over j, store psT[j][r]
#pragma unroll
        for (int it = 0; it < 32; it++) {
            int idx = tid + it*128;               // 4096 elems (32 rows x 128 j)
            int r = idx >> 7, j = idx & 127;
            float p = (j0 + j < SS) ? pg[(size_t)r*SS + j0 + j] : 0.f;
            psT[j*PTS + r] = p;
        }
        __syncthreads();

#pragma unroll 8
        for (int j = 0; j < JT; j++) {
            float4 a4 = *(const float4*)&psT[j*PTS + rg*4];
            float4 b4 = *(const float4*)&vs[j*64 + cg*4];
            float av[4] = {a4.x, a4.y, a4.z, a4.w};
            float bw[4] = {b4.x, b4.y, b4.z, b4.w};
#pragma unroll
            for (int i = 0; i < 4; i++)
#pragma unroll
                for (int c = 0; c < 4; c++)
                    acc[i][c] += av[i] * bw[c];
        }
    }

#pragma unroll
    for (int i = 0; i < 4; i++) {
        float* dst = g_ctx + ((size_t)b*SS + i0 + rg*4 + i)*DD + h*DK + cg*4;
        *(float4*)dst = make_float4(acc[i][0], acc[i][1], acc[i][2], acc[i][3]);
    }
}

// ---------------------------------------------------------------------------
// Kernel 5: output projection.  Same 8x8 scheme as proj_qkv.
// ---------------------------------------------------------------------------
__global__ __launch_bounds__(128) void out_proj(
    const float* __restrict__ wo, const float* __restrict__ bo,
    float* __restrict__ out)
{
    __shared__ float Xs[32][132];
    __shared__ float Ws[32][68];

    const int m0 = blockIdx.x * 64;
    const int n0 = blockIdx.y * 128;
    const int tid = threadIdx.x;

    const int c8 = tid & 7,  xrow = tid >> 3;
    const int wc4 = tid & 15, wk_ = tid >> 4;
    const int ri = tid >> 3, ci = tid & 7;

    float acc[8][8] = {};

    for (int k0 = 0; k0 < DD; k0 += 32) {
#pragma unroll
        for (int rr = 0; rr < 8; rr++) {
            int r = xrow + rr*16;
            float4 v = *(const float4*)&g_ctx[(size_t)(n0 + r)*DD + k0 + c8*4];
            Xs[c8*4+0][r] = v.x; Xs[c8*4+1][r] = v.y;
            Xs[c8*4+2][r] = v.z; Xs[c8*4+3][r] = v.w;
        }
#pragma unroll
        for (int tt = 0; tt < 4; tt++) {
            int k = wk_ + tt*8;
            float4 v = *(const float4*)&wo[(size_t)(k0 + k)*DD + m0 + wc4*4];
            *(float4*)&Ws[k][wc4*4] = v;
        }
        __syncthreads();
#pragma unroll
        for (int t = 0; t < 32; t++) {
            float4 a0 = *(const float4*)&Xs[t][ri*8];
            float4 a1 = *(const float4*)&Xs[t][ri*8+4];
            float4 b0 = *(const float4*)&Ws[t][ci*8];
            float4 b1 = *(const float4*)&Ws[t][ci*8+4];
            float av[8] = {a0.x,a0.y,a0.z,a0.w,a1.x,a1.y,a1.z,a1.w};
            float bw[8] = {b0.x,b0.y,b0.z,b0.w,b1.x,b1.y,b1.z,b1.w};
#pragma unroll
            for (int i = 0; i < 8; i++)
#pragma unroll
                for (int j = 0; j < 8; j++)
                    acc[i][j] += av[i] * bw[j];
        }
        __syncthreads();
    }

    const int d = ci*8;
    float4 bb0 = *(const float4*)&bo[m0 + d];
    float4 bb1 = *(const float4*)&bo[m0 + d + 4];
#pragma unroll
    for (int u = 0; u < 8; u++) {
        int n = n0 + ri*8 + u;
        float* dst = &out[(size_t)n*DD + m0 + d];
        *(float4*)&dst[0] = make_float4(acc[u][0]+bb0.x, acc[u][1]+bb0.y,
                                        acc[u][2]+bb0.z, acc[u][3]+bb0.w);
        *(float4*)&dst[4] = make_float4(acc[u][4]+bb1.x, acc[u][5]+bb1.y,
                                        acc[u][6]+bb1.z, acc[u][7]+bb1.w);
    }
}

// ---------------------------------------------------------------------------

static const int SC_SMEM = (QT*SS + 64*QTP + 64*JTP) * (int)sizeof(float); // 104448
static const int PV_SMEM = (JT*PTS + JT*64) * (int)sizeof(float);          // 51200

extern "C" void kernel_launch(void* const* d_in, const int* in_sizes, int n_in,
                              void* d_out, int out_size) {
    const float* x  = (const float*)d_in[0];
    const float* wq = (const float*)d_in[1];
    const float* bq = (const float*)d_in[2];
    const float* wk = (const float*)d_in[3];
    const float* bk = (const float*)d_in[4];
    const float* wv = (const float*)d_in[5];
    const float* bv = (const float*)d_in[6];
    const float* wo = (const float*)d_in[7];
    const float* bo = (const float*)d_in[8];
    const float* rb = (const float*)d_in[9];

    float* out      = (float*)d_out;
    float* out_attn = out + (size_t)BB*SS*DD;

    proj_qkv<<<dim3(DD/64, (BB*SS)/128, 3), 128>>>(x, wq, bq, wk, bk, wv, bv);

    cudaFuncSetAttribute(scores_kernel, cudaFuncAttributeMaxDynamicSharedMemorySize, SC_SMEM);
    scores_kernel<<<dim3(SS/QT, HH, BB), 256, SC_SMEM>>>(rb);

    mean_kernel<<<(BB*SS*(SS/4))/256, 256>>>(out_attn);

    cudaFuncSetAttribute(pv_kernel, cudaFuncAttributeMaxDynamicSharedMemorySize, PV_SMEM);
    pv_kernel<<<dim3(SS/QT, HH, BB), 128, PV_SMEM>>>();

    out_proj<<<dim3(DD/64, (BB*SS)/128), 128>>>(wo, bo, out);
}

// round 10
// speedup vs baseline: 1.3534x; 1.0313x over previous
#include <cuda_runtime.h>
#include <math_constants.h>
#include <cstdint>

#define BB 32
#define SS 480
#define DD 512
#define HH 8
#define DK 64
#define ML 500
#define QT 32
#define JT 128
#define QTP 36
#define JTP 132
#define PVQ 64      // pv rows per CTA
#define PVP 68      // psT row stride (words, 16B-aligned)

__device__ float g_q[BB*HH*SS*DK];
__device__ float g_k[BB*HH*SS*DK];
__device__ float g_v[BB*HH*SS*DK];
__device__ float g_ctx[(size_t)BB*SS*DD];
__device__ float g_p[(size_t)BB*HH*SS*SS];   // probs

// ---------------------------------------------------------------------------
// Kernel 1: fused QKV projection.  128 threads, tile 128x64, thread tile 8x8,
// BK=32, register-prefetch software pipeline (LDG overlapped with compute).
// ---------------------------------------------------------------------------
__global__ __launch_bounds__(128) void proj_qkv(
    const float* __restrict__ x,
    const float* __restrict__ wq, const float* __restrict__ bq,
    const float* __restrict__ wk, const float* __restrict__ bk,
    const float* __restrict__ wv, const float* __restrict__ bv)
{
    const int z = blockIdx.z;
    const float* W    = (z == 0) ? wq : (z == 1) ? wk : wv;
    const float* bias = (z == 0) ? bq : (z == 1) ? bk : bv;
    float* Out        = (z == 0) ? g_q : (z == 1) ? g_k : g_v;

    __shared__ float Xs[32][132];
    __shared__ float Ws[32][68];

    const int m0 = blockIdx.x * 64;
    const int n0 = blockIdx.y * 128;
    const int tid = threadIdx.x;

    const int c8 = tid & 7,  xrow = tid >> 3;   // X: float4 col, row base
    const int wc4 = tid & 15, wk_ = tid >> 4;   // W: float4 col, k base
    const int ri = tid >> 3, ci = tid & 7;      // compute map

    float acc[8][8] = {};
    float4 xr[8], wr[4];

    // prologue: prefetch k0 = 0
#pragma unroll
    for (int rr = 0; rr < 8; rr++)
        xr[rr] = *(const float4*)&x[(size_t)(n0 + xrow + rr*16)*DD + c8*4];
#pragma unroll
    for (int tt = 0; tt < 4; tt++)
        wr[tt] = *(const float4*)&W[(size_t)(wk_ + tt*8)*DD + m0 + wc4*4];

    for (int k0 = 0; k0 < DD; k0 += 32) {
        // stage prefetched regs into smem
#pragma unroll
        for (int rr = 0; rr < 8; rr++) {
            int r = xrow + rr*16;
            Xs[c8*4+0][r] = xr[rr].x; Xs[c8*4+1][r] = xr[rr].y;
            Xs[c8*4+2][r] = xr[rr].z; Xs[c8*4+3][r] = xr[rr].w;
        }
#pragma unroll
        for (int tt = 0; tt < 4; tt++)
            *(float4*)&Ws[wk_ + tt*8][wc4*4] = wr[tt];
        __syncthreads();

        // prefetch next tile (overlaps with compute below)
        if (k0 + 32 < DD) {
#pragma unroll
            for (int rr = 0; rr < 8; rr++)
                xr[rr] = *(const float4*)&x[(size_t)(n0 + xrow + rr*16)*DD + k0 + 32 + c8*4];
#pragma unroll
            for (int tt = 0; tt < 4; tt++)
                wr[tt] = *(const float4*)&W[(size_t)(k0 + 32 + wk_ + tt*8)*DD + m0 + wc4*4];
        }

#pragma unroll
        for (int t = 0; t < 32; t++) {
            float4 a0 = *(const float4*)&Xs[t][ri*8];
            float4 a1 = *(const float4*)&Xs[t][ri*8+4];
            float4 b0 = *(const float4*)&Ws[t][ci*8];
            float4 b1 = *(const float4*)&Ws[t][ci*8+4];
            float av[8] = {a0.x,a0.y,a0.z,a0.w,a1.x,a1.y,a1.z,a1.w};
            float bw[8] = {b0.x,b0.y,b0.z,b0.w,b1.x,b1.y,b1.z,b1.w};
#pragma unroll
            for (int i = 0; i < 8; i++)
#pragma unroll
                for (int j = 0; j < 8; j++)
                    acc[i][j] += av[i] * bw[j];
        }
        __syncthreads();
    }

    const int h = m0 >> 6;
    const int d = ci*8;
    float4 bb0 = *(const float4*)&bias[m0 + d];
    float4 bb1 = *(const float4*)&bias[m0 + d + 4];
#pragma unroll
    for (int u = 0; u < 8; u++) {
        int n = n0 + ri*8 + u;
        int b = n / SS, s = n % SS;
        float* dst = &Out[(((size_t)b*HH + h)*SS + s)*DK + d];
        *(float4*)&dst[0] = make_float4(acc[u][0]+bb0.x, acc[u][1]+bb0.y,
                                        acc[u][2]+bb0.z, acc[u][3]+bb0.w);
        *(float4*)&dst[4] = make_float4(acc[u][4]+bb1.x, acc[u][5]+bb1.y,
                                        acc[u][6]+bb1.z, acc[u][7]+bb1.w);
    }
}

// ---------------------------------------------------------------------------
// Kernel 2: scores + softmax + write probs P.  (unchanged — known good)
// ---------------------------------------------------------------------------
__global__ __launch_bounds__(256, 2) void scores_kernel(
    const float* __restrict__ rel_bias)
{
    extern __shared__ float smem[];
    float* sc  = smem;
    float* qsT = sc + QT*SS;
    float* kvb = qsT + 64*QTP;

    const int i0 = blockIdx.x * QT;
    const int h  = blockIdx.y;
    const int b  = blockIdx.z;
    const int tid = threadIdx.x;
    const int lane = tid & 31, warp = tid >> 5;

    const int jcount = i0 + QT;
    const int ntile  = (jcount + JT - 1) / JT;
    const int jcap   = min(SS, ntile * JT);

    const float* qg = g_q + (((size_t)b*HH + h)*SS + i0)*DK;
    const float* kg = g_k + (((size_t)b*HH + h)*SS)*DK;

    for (int idx = tid; idx < QT*DK; idx += 256) {
        int i = idx >> 6, t = idx & 63;
        qsT[t*QTP + i] = qg[idx];
    }

    for (int jt = 0; jt < ntile; jt++) {
        int j0 = jt * JT;
        __syncthreads();
        for (int idx = tid; idx < JT*DK; idx += 256) {
            int jl = idx >> 6, t = idx & 63;
            int j = j0 + jl;
            kvb[t*JTP + jl] = (j < SS) ? kg[(size_t)j*DK + t] : 0.f;
        }
        __syncthreads();
        const int ti = (tid >> 5) * 4;
        const int tj = (tid & 31) * 4;
        float acc[4][4] = {};
#pragma unroll
        for (int t = 0; t < 64; t++) {
            float4 a4 = *(const float4*)&qsT[t*QTP + ti];
            float4 b4 = *(const float4*)&kvb[t*JTP + tj];
            float av[4] = {a4.x, a4.y, a4.z, a4.w};
            float bw[4] = {b4.x, b4.y, b4.z, b4.w};
#pragma unroll
            for (int i = 0; i < 4; i++)
#pragma unroll
                for (int j = 0; j < 4; j++)
                    acc[i][j] += av[i] * bw[j];
        }
#pragma unroll
        for (int ii = 0; ii < 4; ii++) {
            int i = i0 + ti + ii;
            const float* brow = rel_bias + ((size_t)h*ML + i)*ML;
            float4 bias4;
            if (j0 + tj + 3 < SS) bias4 = *(const float4*)&brow[j0 + tj];
            else {
                bias4.x = (j0+tj   < SS) ? brow[j0+tj]   : 0.f;
                bias4.y = (j0+tj+1 < SS) ? brow[j0+tj+1] : 0.f;
                bias4.z = (j0+tj+2 < SS) ? brow[j0+tj+2] : 0.f;
                bias4.w = (j0+tj+3 < SS) ? brow[j0+tj+3] : 0.f;
            }
            float bb4[4] = {bias4.x, bias4.y, bias4.z, bias4.w};
            float vals[4];
#pragma unroll
            for (int jj = 0; jj < 4; jj++) {
                int j = j0 + tj + jj;
                vals[jj] = (j <= i && j < SS) ? acc[ii][jj]*0.125f + bb4[jj]
                                              : -CUDART_INF_F;
            }
            if (j0 + JT <= SS) {
                *(float4*)&sc[(ti+ii)*SS + j0 + tj] =
                    make_float4(vals[0], vals[1], vals[2], vals[3]);
            } else {
#pragma unroll
                for (int jj = 0; jj < 4; jj++) {
                    int j = j0 + tj + jj;
                    if (j < SS) sc[(ti+ii)*SS + j] = vals[jj];
                }
            }
        }
    }
    __syncthreads();

    for (int r = warp; r < QT; r += 8) {
        float* row = sc + r*SS;
        float m = -CUDART_INF_F;
        for (int j = lane; j < jcap; j += 32) m = fmaxf(m, row[j]);
#pragma unroll
        for (int o = 16; o; o >>= 1) m = fmaxf(m, __shfl_xor_sync(0xffffffffu, m, o));
        float ssum = 0.f;
        for (int j = lane; j < jcap; j += 32) {
            float e = __expf(row[j] - m);
            row[j] = e;
            ssum += e;
        }
#pragma unroll
        for (int o = 16; o; o >>= 1) ssum += __shfl_xor_sync(0xffffffffu, ssum, o);
        float inv = 1.f / ssum;
        for (int j = lane; j < jcap; j += 32) row[j] *= inv;
    }
    __syncthreads();

    float* pg = g_p + (((size_t)b*HH + h)*SS + i0)*SS;
    const int nq4 = jcap >> 2;
    for (int idx = tid; idx < QT*nq4; idx += 256) {
        int r = idx / nq4, c4 = idx - r*nq4;
        *(float4*)&pg[(size_t)r*SS + c4*4] = *(const float4*)&sc[r*SS + c4*4];
    }
}

// ---------------------------------------------------------------------------
// Kernel 3: attn mean over heads.  (unchanged)
// ---------------------------------------------------------------------------
__global__ __launch_bounds__(256) void mean_kernel(float* __restrict__ out_attn)
{
    const int gid = blockIdx.x * 256 + threadIdx.x;
    const int j4  = gid % (SS/4);
    int rest = gid / (SS/4);
    const int i = rest % SS;
    const int b = rest / SS;

    const int i0 = (i >> 5) << 5;
    const int jcap = min(SS, (((i0 + QT) + JT - 1) / JT) * JT);

    float4 s = make_float4(0.f, 0.f, 0.f, 0.f);
    if (j4*4 < jcap) {
        const float* base = g_p + (((size_t)b*HH)*SS + i)*SS + j4*4;
#pragma unroll
        for (int h = 0; h < HH; h++) {
            float4 v = *(const float4*)(base + (size_t)h*SS*SS);
            s.x += v.x; s.y += v.y; s.z += v.z; s.w += v.w;
        }
        s.x *= 0.125f; s.y *= 0.125f; s.z *= 0.125f; s.w *= 0.125f;
    }
    *(float4*)&out_attn[((size_t)b*SS + i)*SS + j4*4] = s;
}

// ---------------------------------------------------------------------------
// Kernel 4: ctx = P @ V.  256 threads, C tile 64x64, thread tile 4x4.
// P transposed in smem (psT[j][r], zero-padded), V as vs[j][d].
// 67.6 KB smem -> 3 CTAs/SM.
// ---------------------------------------------------------------------------
__global__ __launch_bounds__(256) void pv_kernel()
{
    extern __shared__ float pvsm[];
    float* psT = pvsm;              // JT * PVP
    float* vs  = psT + JT*PVP;      // JT * 64

    const int i0 = blockIdx.x * PVQ;
    const int h  = blockIdx.y;
    const int b  = blockIdx.z;
    const int tid = threadIdx.x;

    const int jcount = min(i0 + PVQ, SS);
    const int ntile  = (jcount + JT - 1) / JT;

    const float* vg = g_v + (((size_t)b*HH + h)*SS)*DK;
    const float* pg = g_p + (((size_t)b*HH + h)*SS + i0)*SS;

    const int rg = tid >> 4;      // 16 rowgroups of 4  (64 rows)
    const int cg = tid & 15;      // 16 colgroups of 4  (64 cols)

    float acc[4][4] = {};

    for (int jt = 0; jt < ntile; jt++) {
        const int j0 = jt * JT;
        __syncthreads();
        // V tile [j][d]: 2048 float4 / 256 thr = 8 iters
#pragma unroll
        for (int it = 0; it < 8; it++) {
            int idx = tid + it*256;
            int j = idx >> 4, d4 = idx & 15;
            float4 v = (j0 + j < SS)
                ? *(const float4*)&vg[(size_t)(j0 + j)*DK + d4*4]
                : make_float4(0.f,0.f,0.f,0.f);
            *(float4*)&vs[j*64 + d4*4] = v;
        }
        // P tile transposed: 64 rows x 128 j = 8192 scalars / 256 = 32 iters
#pragma unroll
        for (int it = 0; it < 32; it++) {
            int idx = tid + it*256;
            int r = idx >> 7, j = idx & 127;
            float p = (i0 + r < SS && j0 + j < SS) ? pg[(size_t)r*SS + j0 + j] : 0.f;
            psT[j*PVP + r] = p;
        }
        __syncthreads();

#pragma unroll 8
        for (int j = 0; j < JT; j++) {
            float4 a4 = *(const float4*)&psT[j*PVP + rg*4];
            float4 b4 = *(const float4*)&vs[j*64 + cg*4];
            float av[4] = {a4.x, a4.y, a4.z, a4.w};
            float bw[4] = {b4.x, b4.y, b4.z, b4.w};
#pragma unroll
            for (int i = 0; i < 4; i++)
#pragma unroll
                for (int c = 0; c < 4; c++)
                    acc[i][c] += av[i] * bw[c];
        }
    }

#pragma unroll
    for (int i = 0; i < 4; i++) {
        int row = i0 + rg*4 + i;
        if (row < SS) {
            float* dst = g_ctx + ((size_t)b*SS + row)*DD + h*DK + cg*4;
            *(float4*)dst = make_float4(acc[i][0], acc[i][1], acc[i][2], acc[i][3]);
        }
    }
}

// ---------------------------------------------------------------------------
// Kernel 5: output projection.  Same 8x8 + prefetch scheme as proj_qkv.
// ---------------------------------------------------------------------------
__global__ __launch_bounds__(128) void out_proj(
    const float* __restrict__ wo, const float* __restrict__ bo,
    float* __restrict__ out)
{
    __shared__ float Xs[32][132];
    __shared__ float Ws[32][68];

    const int m0 = blockIdx.x * 64;
    const int n0 = blockIdx.y * 128;
    const int tid = threadIdx.x;

    const int c8 = tid & 7,  xrow = tid >> 3;
    const int wc4 = tid & 15, wk_ = tid >> 4;
    const int ri = tid >> 3, ci = tid & 7;

    float acc[8][8] = {};
    float4 xr[8], wr[4];

#pragma unroll
    for (int rr = 0; rr < 8; rr++)
        xr[rr] = *(const float4*)&g_ctx[(size_t)(n0 + xrow + rr*16)*DD + c8*4];
#pragma unroll
    for (int tt = 0; tt < 4; tt++)
        wr[tt] = *(const float4*)&wo[(size_t)(wk_ + tt*8)*DD + m0 + wc4*4];

    for (int k0 = 0; k0 < DD; k0 += 32) {
#pragma unroll
        for (int rr = 0; rr < 8; rr++) {
            int r = xrow + rr*16;
            Xs[c8*4+0][r] = xr[rr].x; Xs[c8*4+1][r] = xr[rr].y;
            Xs[c8*4+2][r] = xr[rr].z; Xs[c8*4+3][r] = xr[rr].w;
        }
#pragma unroll
        for (int tt = 0; tt < 4; tt++)
            *(float4*)&Ws[wk_ + tt*8][wc4*4] = wr[tt];
        __syncthreads();

        if (k0 + 32 < DD) {
#pragma unroll
            for (int rr = 0; rr < 8; rr++)
                xr[rr] = *(const float4*)&g_ctx[(size_t)(n0 + xrow + rr*16)*DD + k0 + 32 + c8*4];
#pragma unroll
            for (int tt = 0; tt < 4; tt++)
                wr[tt] = *(const float4*)&wo[(size_t)(k0 + 32 + wk_ + tt*8)*DD + m0 + wc4*4];
        }

#pragma unroll
        for (int t = 0; t < 32; t++) {
            float4 a0 = *(const float4*)&Xs[t][ri*8];
            float4 a1 = *(const float4*)&Xs[t][ri*8+4];
            float4 b0 = *(const float4*)&Ws[t][ci*8];
            float4 b1 = *(const float4*)&Ws[t][ci*8+4];
            float av[8] = {a0.x,a0.y,a0.z,a0.w,a1.x,a1.y,a1.z,a1.w};
            float bw[8] = {b0.x,b0.y,b0.z,b0.w,b1.x,b1.y,b1.z,b1.w};
#pragma unroll
            for (int i = 0; i < 8; i++)
#pragma unroll
                for (int j = 0; j < 8; j++)
                    acc[i][j] += av[i] * bw[j];
        }
        __syncthreads();
    }

    const int d = ci*8;
    float4 bb0 = *(const float4*)&bo[m0 + d];
    float4 bb1 = *(const float4*)&bo[m0 + d + 4];
#pragma unroll
    for (int u = 0; u < 8; u++) {
        int n = n0 + ri*8 + u;
        float* dst = &out[(size_t)n*DD + m0 + d];
        *(float4*)&dst[0] = make_float4(acc[u][0]+bb0.x, acc[u][1]+bb0.y,
                                        acc[u][2]+bb0.z, acc[u][3]+bb0.w);
        *(float4*)&dst[4] = make_float4(acc[u][4]+bb1.x, acc[u][5]+bb1.y,
                                        acc[u][6]+bb1.z, acc[u][7]+bb1.w);
    }
}

// ---------------------------------------------------------------------------

static const int SC_SMEM = (QT*SS + 64*QTP + 64*JTP) * (int)sizeof(float); // 104448
static const int PV_SMEM = (JT*PVP + JT*64) * (int)sizeof(float);          // 67584

extern "C" void kernel_launch(void* const* d_in, const int* in_sizes, int n_in,
                              void* d_out, int out_size) {
    const float* x  = (const float*)d_in[0];
    const float* wq = (const float*)d_in[1];
    const float* bq = (const float*)d_in[2];
    const float* wk = (const float*)d_in[3];
    const float* bk = (const float*)d_in[4];
    const float* wv = (const float*)d_in[5];
    const float* bv = (const float*)d_in[6];
    const float* wo = (const float*)d_in[7];
    const float* bo = (const float*)d_in[8];
    const float* rb = (const float*)d_in[9];

    float* out      = (float*)d_out;
    float* out_attn = out + (size_t)BB*SS*DD;

    cudaFuncSetAttribute(scores_kernel, cudaFuncAttributeMaxDynamicSharedMemorySize, SC_SMEM);
    cudaFuncSetAttribute(pv_kernel, cudaFuncAttributeMaxDynamicSharedMemorySize, PV_SMEM);

    proj_qkv<<<dim3(DD/64, (BB*SS)/128, 3), 128>>>(x, wq, bq, wk, bk, wv, bv);

    scores_kernel<<<dim3(SS/QT, HH, BB), 256, SC_SMEM>>>(rb);

    mean_kernel<<<(BB*SS*(SS/4))/256, 256>>>(out_attn);

    pv_kernel<<<dim3((SS + PVQ - 1)/PVQ, HH, BB), 256, PV_SMEM>>>();

    out_proj<<<dim3(DD/64, (BB*SS)/128), 128>>>(wo, bo, out);
}